// round 17
// baseline (speedup 1.0000x reference)
#include <cuda_runtime.h>
#include <cuda_bf16.h>
#include <cuda_fp16.h>
#include <cstdint>

#define B 2
#define S 2048
#define HIDDEN 896
#define NH 14
#define NKV 2
#define HD 64
#define NREP 7
#define MTOK (B*S)          // 4096 tokens

// element counts (float4 units)
#define NX4  (MTOK*HIDDEN/4)
#define NQ4  (HIDDEN*HIDDEN/4)
#define NK4  (NKV*HD*HIDDEN/4)
#define NV4  NK4
#define NO4  NQ4
#define TOT4 (NX4 + NQ4 + NK4 + NV4 + NO4)

// ---------------- scratch (device globals) ----------------
__device__ __half g_qh[B * NH * S * HD];       // [b,h,s,d] fp16 (pre-scaled by ASCALE)
__device__ __half g_kh[B * NKV * S * HD];      // [b,kv,s,d] fp16
__device__ __half g_vth[B * NKV * HD * S];     // [b,kv,d,s] fp16 TRANSPOSED
__device__ float2 g_rope[S * 32];

// fp16 pre-converted operands (uint2 = 4 fp16)
__device__ uint2 g_xh[NX4];                    // hidden_states (single fp16)
__device__ uint2 g_wqh[NQ4], g_wkh[NK4], g_wvh[NV4], g_woh[NO4];
__device__ uint2 g_ah[NX4], g_al[NX4];         // attention output (fp16 hi/lo)

// Q pre-scale: 1/sqrt(64) * log2(e)
#define ASCALE 0.1803368801111204f

// ---------------- helpers ----------------
__device__ __forceinline__ void mma_f16(float* d, const uint32_t* a, uint32_t b0, uint32_t b1) {
    asm volatile(
        "mma.sync.aligned.m16n8k16.row.col.f32.f16.f16.f32 "
        "{%0,%1,%2,%3}, {%4,%5,%6,%7}, {%8,%9}, {%0,%1,%2,%3};\n"
        : "+f"(d[0]), "+f"(d[1]), "+f"(d[2]), "+f"(d[3])
        : "r"(a[0]), "r"(a[1]), "r"(a[2]), "r"(a[3]), "r"(b0), "r"(b1));
}

#define LDSM_X4(r0, r1, r2, r3, addr) \
    asm volatile("ldmatrix.sync.aligned.m8n8.x4.shared.b16 {%0,%1,%2,%3}, [%4];" \
                 : "=r"(r0), "=r"(r1), "=r"(r2), "=r"(r3) : "r"(addr))

#define CP_ASYNC16(dst, src) \
    asm volatile("cp.async.ca.shared.global [%0], [%1], 16;" :: "r"(dst), "l"(src))
#define CP_COMMIT() asm volatile("cp.async.commit_group;" ::: "memory")
#define CP_WAIT(n)  asm volatile("cp.async.wait_group %0;" :: "n"(n) : "memory")

// pack two floats into fp16x2 (x0 -> low half)
__device__ __forceinline__ uint32_t pack_h2(float x0, float x1) {
    uint32_t r;
    asm("cvt.rn.f16x2.f32 %0, %1, %2;" : "=r"(r) : "f"(x1), "f"(x0));
    return r;
}

// fp16 hi/lo split of two floats
__device__ __forceinline__ void split2h(float x0, float x1, uint32_t& hi, uint32_t& lo) {
    hi = pack_h2(x0, x1);
    float h0, h1;
    asm("{\n\t.reg .b16 l, h;\n\tmov.b32 {l, h}, %2;\n\t"
        "cvt.f32.f16 %0, l;\n\tcvt.f32.f16 %1, h;\n\t}"
        : "=f"(h0), "=f"(h1) : "r"(hi));
    lo = pack_h2(x0 - h0, x1 - h1);
}

// ---------------- conversion pass: fp32 -> fp16 ----------------
__global__ void conv_h(const float4* __restrict__ x,
                       const float4* __restrict__ wq,
                       const float4* __restrict__ wk,
                       const float4* __restrict__ wv,
                       const float4* __restrict__ wo) {
    int i = blockIdx.x * blockDim.x + threadIdx.x;
    if (i >= TOT4) return;
    const float4* src;
    uint2* dst;
    int off = i;
    if (off < NX4)                    { src = x;  dst = g_xh; }
    else if ((off -= NX4) < NQ4)      { src = wq; dst = g_wqh; }
    else if ((off -= NQ4) < NK4)      { src = wk; dst = g_wkh; }
    else if ((off -= NK4) < NV4)      { src = wv; dst = g_wvh; }
    else { off -= NV4;                  src = wo; dst = g_woh; }
    float4 v = src[off];
    dst[off] = make_uint2(pack_h2(v.x, v.y), pack_h2(v.z, v.w));
}

// ---------------- rope table ----------------
__global__ void build_rope(float2* tab) {
    int idx = blockIdx.x * blockDim.x + threadIdx.x;
    int s = idx >> 5, i = idx & 31;
    const float LOG2_THETA_OVER_32 = 0.62286105580517513f;
    float inv = exp2f(-(float)i * LOG2_THETA_OVER_32);
    float sn, cs;
    sincosf((float)s * inv, &sn, &cs);
    tab[idx] = make_float2(cs, sn);
}

// ======== fp16 GEMM cores: CTA 128x64, 128 thr, BK=64, double-buffered ========
#define GP 144
#define G1_A 0
#define G1_B (128 * GP)
#define G1_BUF (128 * GP + 64 * GP)
#define G1_SMEM (2 * G1_BUF)
#define G2_AH 0
#define G2_AL (128 * GP)
#define G2_B  (2 * 128 * GP)
#define G2_BUF (2 * 128 * GP + 64 * GP)
#define G2_SMEM (2 * G2_BUF)
#define NKC (HIDDEN / 64)               // 14

// single-term: c = A(fp16) * B(fp16)^T
__device__ __forceinline__ void gemm1_core(const char* __restrict__ Ah,
                                           const char* __restrict__ Bh,
                                           int m0, float c[2][8][4],
                                           char* smem, int tid) {
    const int w = tid >> 5;
    const int lane = tid & 31;
    const uint32_t sb = (uint32_t)__cvta_generic_to_shared(smem);

    const int arow = (lane & 7) + ((lane >> 3) & 1) * 8;
    const int acol = (lane >> 4) * 16;
    const int brow = (lane & 7) + ((lane >> 4) & 1) * 8;
    const int bcol = ((lane >> 3) & 1) * 16;

#pragma unroll
    for (int mg = 0; mg < 2; mg++)
#pragma unroll
        for (int nf = 0; nf < 8; nf++)
#pragma unroll
            for (int j = 0; j < 4; j++) c[mg][nf][j] = 0.f;

    auto stage = [&](int kc, int buf) {
        uint32_t base = sb + buf * G1_BUF;
#pragma unroll
        for (int t = 0; t < 8; t++) {
            int i = tid + t * 128;
            int r = i >> 3, j = i & 7;
            CP_ASYNC16(base + G1_A + r * GP + j * 16,
                       Ah + ((size_t)(m0 + r) * HIDDEN + kc * 64) * 2 + j * 16);
        }
#pragma unroll
        for (int t = 0; t < 4; t++) {
            int i = tid + t * 128;
            int r = i >> 3, j = i & 7;
            CP_ASYNC16(base + G1_B + r * GP + j * 16,
                       Bh + ((size_t)r * HIDDEN + kc * 64) * 2 + j * 16);
        }
    };

    stage(0, 0);
    CP_COMMIT();

    for (int kc = 0; kc < NKC; kc++) {
        if (kc + 1 < NKC) {
            stage(kc + 1, (kc + 1) & 1);
            CP_COMMIT();
            CP_WAIT(1);
        } else {
            CP_WAIT(0);
        }
        __syncthreads();

        uint32_t base = sb + (kc & 1) * G1_BUF;
#pragma unroll
        for (int ks = 0; ks < 4; ks++) {
            uint32_t a[2][4];
#pragma unroll
            for (int mg = 0; mg < 2; mg++) {
                uint32_t aaddr = base + G1_A + (w * 32 + mg * 16 + arow) * GP + acol + ks * 32;
                LDSM_X4(a[mg][0], a[mg][1], a[mg][2], a[mg][3], aaddr);
            }
#pragma unroll
            for (int np = 0; np < 4; np++) {
                uint32_t baddr = base + G1_B + (np * 16 + brow) * GP + bcol + ks * 32;
                uint32_t b0, b1, b2, b3;
                LDSM_X4(b0, b1, b2, b3, baddr);
#pragma unroll
                for (int mg = 0; mg < 2; mg++) {
                    mma_f16(c[mg][2 * np], a[mg], b0, b1);
                    mma_f16(c[mg][2 * np + 1], a[mg], b2, b3);
                }
            }
        }
        __syncthreads();
    }
}

// two-term A: c = (Ahi + Alo)(fp16) * B(fp16)^T
__device__ __forceinline__ void gemm2_core(const char* __restrict__ Ahi,
                                           const char* __restrict__ Alo,
                                           const char* __restrict__ Bh,
                                           int m0, float c[2][8][4],
                                           char* smem, int tid) {
    const int w = tid >> 5;
    const int lane = tid & 31;
    const uint32_t sb = (uint32_t)__cvta_generic_to_shared(smem);

    const int arow = (lane & 7) + ((lane >> 3) & 1) * 8;
    const int acol = (lane >> 4) * 16;
    const int brow = (lane & 7) + ((lane >> 4) & 1) * 8;
    const int bcol = ((lane >> 3) & 1) * 16;

#pragma unroll
    for (int mg = 0; mg < 2; mg++)
#pragma unroll
        for (int nf = 0; nf < 8; nf++)
#pragma unroll
            for (int j = 0; j < 4; j++) c[mg][nf][j] = 0.f;

    auto stage = [&](int kc, int buf) {
        uint32_t base = sb + buf * G2_BUF;
#pragma unroll
        for (int t = 0; t < 8; t++) {
            int i = tid + t * 128;
            int r = i >> 3, j = i & 7;
            size_t go = ((size_t)(m0 + r) * HIDDEN + kc * 64) * 2 + j * 16;
            CP_ASYNC16(base + G2_AH + r * GP + j * 16, Ahi + go);
            CP_ASYNC16(base + G2_AL + r * GP + j * 16, Alo + go);
        }
#pragma unroll
        for (int t = 0; t < 4; t++) {
            int i = tid + t * 128;
            int r = i >> 3, j = i & 7;
            CP_ASYNC16(base + G2_B + r * GP + j * 16,
                       Bh + ((size_t)r * HIDDEN + kc * 64) * 2 + j * 16);
        }
    };

    stage(0, 0);
    CP_COMMIT();

    for (int kc = 0; kc < NKC; kc++) {
        if (kc + 1 < NKC) {
            stage(kc + 1, (kc + 1) & 1);
            CP_COMMIT();
            CP_WAIT(1);
        } else {
            CP_WAIT(0);
        }
        __syncthreads();

        uint32_t base = sb + (kc & 1) * G2_BUF;
#pragma unroll
        for (int ks = 0; ks < 4; ks++) {
            uint32_t ah[2][4], al[2][4];
#pragma unroll
            for (int mg = 0; mg < 2; mg++) {
                uint32_t aaddr = base + G2_AH + (w * 32 + mg * 16 + arow) * GP + acol + ks * 32;
                LDSM_X4(ah[mg][0], ah[mg][1], ah[mg][2], ah[mg][3], aaddr);
                LDSM_X4(al[mg][0], al[mg][1], al[mg][2], al[mg][3], aaddr + (G2_AL - G2_AH));
            }
#pragma unroll
            for (int np = 0; np < 4; np++) {
                uint32_t baddr = base + G2_B + (np * 16 + brow) * GP + bcol + ks * 32;
                uint32_t b0, b1, b2, b3;
                LDSM_X4(b0, b1, b2, b3, baddr);
#pragma unroll
                for (int mg = 0; mg < 2; mg++) {
                    mma_f16(c[mg][2 * np], ah[mg], b0, b1);
                    mma_f16(c[mg][2 * np], al[mg], b0, b1);
                    mma_f16(c[mg][2 * np + 1], ah[mg], b2, b3);
                    mma_f16(c[mg][2 * np + 1], al[mg], b2, b3);
                }
            }
        }
        __syncthreads();
    }
}

// ---- fused QKV projection (single fp16) + bias + RoPE + fp16 outputs ----
__global__ __launch_bounds__(128) void gemm_qkv(const float* __restrict__ bq,
                                                const float* __restrict__ bk,
                                                const float* __restrict__ bv,
                                                const float2* __restrict__ rope,
                                                __half* __restrict__ qo,
                                                __half* __restrict__ ko,
                                                __half* __restrict__ vt) {
    extern __shared__ char smem[];
    const int tid = threadIdx.x;
    const int w = tid >> 5;
    const int lane = tid & 31;
    const int lg = lane >> 2;
    const int lt = lane & 3;
    const int nt = blockIdx.x;
    const int m0 = blockIdx.y * 128;

    const char* Bh;
    const float* bias;
    if (nt < 14)      { Bh = (const char*)g_wqh + (size_t)nt * 64 * HIDDEN * 2;        bias = bq + nt * 64; }
    else if (nt < 16) { Bh = (const char*)g_wkh + (size_t)(nt - 14) * 64 * HIDDEN * 2; bias = bk + (nt - 14) * 64; }
    else              { Bh = (const char*)g_wvh + (size_t)(nt - 16) * 64 * HIDDEN * 2; bias = bv + (nt - 16) * 64; }

    float c[2][8][4];
    gemm1_core((const char*)g_xh, Bh, m0, c, smem, tid);

#pragma unroll
    for (int mg = 0; mg < 2; mg++) {
#pragma unroll
        for (int rr = 0; rr < 2; rr++) {
            int row = m0 + w * 32 + mg * 16 + lg + rr * 8;   // token index
            int b = row >> 11;
            int s = row & (S - 1);
            if (nt < 16) {
                const bool isQ = (nt < 14);
                __half* base = isQ
                    ? qo + (((size_t)b * NH + nt) * S + s) * HD
                    : ko + (((size_t)b * NKV + (nt - 14)) * S + s) * HD;
                const float sc = isQ ? ASCALE : 1.0f;
                uint32_t* bw = (uint32_t*)base;
#pragma unroll
                for (int nf = 0; nf < 4; nf++) {
                    int d0 = nf * 8 + 2 * lt;
                    float2 t0 = rope[s * 32 + d0];
                    float2 t1 = rope[s * 32 + d0 + 1];
                    float x10 = c[mg][nf][rr * 2 + 0] + bias[d0];
                    float x11 = c[mg][nf][rr * 2 + 1] + bias[d0 + 1];
                    float x20 = c[mg][nf + 4][rr * 2 + 0] + bias[d0 + 32];
                    float x21 = c[mg][nf + 4][rr * 2 + 1] + bias[d0 + 33];
                    float y10 = (x10 * t0.x - x20 * t0.y) * sc;
                    float y11 = (x11 * t1.x - x21 * t1.y) * sc;
                    float y20 = (x20 * t0.x + x10 * t0.y) * sc;
                    float y21 = (x21 * t1.x + x11 * t1.y) * sc;
                    bw[d0 >> 1] = pack_h2(y10, y11);
                    bw[(d0 + 32) >> 1] = pack_h2(y20, y21);
                }
            } else {
                // V transposed: [b][kv][d][s] fp16
                __half* base = vt + ((size_t)(b * NKV + (nt - 16)) * HD) * S + s;
#pragma unroll
                for (int nf = 0; nf < 8; nf++) {
                    int d0 = nf * 8 + 2 * lt;
                    base[(size_t)d0 * S] = __float2half_rn(c[mg][nf][rr * 2 + 0] + bias[d0]);
                    base[(size_t)(d0 + 1) * S] = __float2half_rn(c[mg][nf][rr * 2 + 1] + bias[d0 + 1]);
                }
            }
        }
    }
}

// ---- output projection: d_out = attn(hi+lo fp16) * Wo(fp16)^T ----
__global__ __launch_bounds__(128) void gemm_out(float* __restrict__ C) {
    extern __shared__ char smem[];
    const int tid = threadIdx.x;
    const int w = tid >> 5;
    const int lane = tid & 31;
    const int lg = lane >> 2;
    const int lt = lane & 3;
    const int n0 = blockIdx.x * 64;
    const int m0 = blockIdx.y * 128;

    float c[2][8][4];
    gemm2_core((const char*)g_ah, (const char*)g_al,
               (const char*)g_woh + (size_t)n0 * HIDDEN * 2,
               m0, c, smem, tid);

#pragma unroll
    for (int mg = 0; mg < 2; mg++) {
        const int row = m0 + w * 32 + mg * 16 + lg;
#pragma unroll
        for (int nf = 0; nf < 8; nf++) {
            int col = n0 + nf * 8 + 2 * lt;
            *reinterpret_cast<float2*>(&C[(size_t)row * HIDDEN + col]) =
                make_float2(c[mg][nf][0], c[mg][nf][1]);
            *reinterpret_cast<float2*>(&C[(size_t)(row + 8) * HIDDEN + col]) =
                make_float2(c[mg][nf][2], c[mg][nf][3]);
        }
    }
}

// -------- Flash attention: paired q-tiles, fp16 mma, double-buffered K/V --------
// CTA handles q-tiles (2pi, 2pi+1) of one head; K/V staged once per key tile.
// Single c array reused: QK_A -> softmax_A -> QK_B -> PV_A -> softmax_B -> PV_B.
// layout: K0 | V0 | K1 | V1 | P_A | P_B  -> 55296 B, 2 CTAs/SM
#define PH 144
#define HTILE (64 * PH)                  // 9216 B per tile
#define ATTN_SMEM (6 * HTILE)            // 55296 B

__global__ __launch_bounds__(128, 2) void attn_kernel(const __half* __restrict__ Q,
                                                      const __half* __restrict__ K,
                                                      const __half* __restrict__ V,   // [d][s]
                                                      uint32_t* __restrict__ Ohi,
                                                      uint32_t* __restrict__ Olo) {
    extern __shared__ char sm_c[];
    const uint32_t sbase = (uint32_t)__cvta_generic_to_shared(sm_c);
    const uint32_t psA = sbase + 4 * HTILE;
    const uint32_t psB = sbase + 5 * HTILE;

    const int pi = gridDim.x - 1 - blockIdx.x;   // heavy pairs launch first
    const int qtA = 2 * pi;
    const int qtB = 2 * pi + 1;
    const int h = blockIdx.y;
    const int b = blockIdx.z;
    const int kvh = h / NREP;
    const int tid = threadIdx.x;
    const int w = tid >> 5;                      // 4 warps
    const int lane = tid & 31;
    const int lg = lane >> 2;
    const int lt = lane & 3;

    const __half* QbA = Q + (((size_t)b * NH + h) * S + (size_t)qtA * 64) * HD;
    const __half* QbB = Q + (((size_t)b * NH + h) * S + (size_t)qtB * 64) * HD;
    const __half* Kb = K + (((size_t)b * NKV + kvh) * S) * HD;
    const __half* Vtb = V + ((size_t)(b * NKV + kvh) * HD) * S;

    // Q fragments for both tiles
    uint32_t aqA[4][4], aqB[4][4];
    {
        const int r0 = w * 16 + lg;
        const uint32_t* a0 = (const uint32_t*)(QbA + (size_t)r0 * HD);
        const uint32_t* a1 = (const uint32_t*)(QbA + (size_t)(r0 + 8) * HD);
        const uint32_t* b0 = (const uint32_t*)(QbB + (size_t)r0 * HD);
        const uint32_t* b1 = (const uint32_t*)(QbB + (size_t)(r0 + 8) * HD);
#pragma unroll
        for (int ks = 0; ks < 4; ks++) {
            aqA[ks][0] = a0[ks * 8 + lt];
            aqA[ks][1] = a1[ks * 8 + lt];
            aqA[ks][2] = a0[ks * 8 + lt + 4];
            aqA[ks][3] = a1[ks * 8 + lt + 4];
            aqB[ks][0] = b0[ks * 8 + lt];
            aqB[ks][1] = b1[ks * 8 + lt];
            aqB[ks][2] = b0[ks * 8 + lt + 4];
            aqB[ks][3] = b1[ks * 8 + lt + 4];
        }
    }

    const int k_row = ((lane >> 4) << 3) + (lane & 7);
    const int k_colb = ((lane >> 3) & 1) * 16;           // bytes
    const int p_row = w * 16 + (lane & 15);
    const int p_colb = (lane >> 4) * 16;                 // bytes

    float oA[8][4], oB[8][4], c[8][4];
#pragma unroll
    for (int n = 0; n < 8; n++)
#pragma unroll
        for (int j = 0; j < 4; j++) { oA[n][j] = 0.f; oB[n][j] = 0.f; }
    float mA0 = -1e30f, mA1 = -1e30f, lA0 = 0.f, lA1 = 0.f;   // l are LANE-PARTIAL
    float mB0 = -1e30f, mB1 = -1e30f, lB0 = 0.f, lB1 = 0.f;

    auto kbase = [&](int buf) { return sbase + (2 * buf) * HTILE; };
    auto vbase = [&](int buf) { return sbase + (2 * buf + 1) * HTILE; };

    auto stage = [&](int kt, int buf) {
        uint32_t kb = kbase(buf);
        uint32_t vb = vbase(buf);
#pragma unroll
        for (int i = tid; i < 1024; i += 128) {
            int isV = i >> 9;
            int idx = i & 511;
            int r = idx >> 3;
            int j = idx & 7;
            if (isV) {
                CP_ASYNC16(vb + (uint32_t)(r * PH + j * 16),
                           (const char*)Vtb + ((size_t)r * S + (size_t)kt * 64) * 2 + j * 16);
            } else {
                CP_ASYNC16(kb + (uint32_t)(r * PH + j * 16),
                           (const char*)Kb + ((size_t)(kt * 64 + r) * HD) * 2 + j * 16);
            }
        }
    };

    auto qk = [&](uint32_t (&aq)[4][4], int buf) {
        uint32_t kb = kbase(buf);
#pragma unroll
        for (int n = 0; n < 8; n++)
#pragma unroll
            for (int j = 0; j < 4; j++) c[n][j] = 0.f;
#pragma unroll
        for (int ks = 0; ks < 4; ks++) {
#pragma unroll
            for (int jp = 0; jp < 4; jp++) {
                uint32_t b0, b1, b2, b3;
                uint32_t addr = kb + (uint32_t)((jp * 16 + k_row) * PH + ks * 32 + k_colb);
                LDSM_X4(b0, b1, b2, b3, addr);
                mma_f16(c[2 * jp], aq[ks], b0, b1);
                mma_f16(c[2 * jp + 1], aq[ks], b2, b3);
            }
        }
    };

    // softmax: mask (if diag), max-reduce, exp2, P->smem fp16, lane-partial l
    auto softmax_t = [&](uint32_t psb, float& m0r, float& m1r, float& l0r, float& l1r,
                         float (&o)[8][4], bool diag) {
        if (diag) {
            const int row0 = w * 16 + lg;
#pragma unroll
            for (int n = 0; n < 8; n++) {
                int col = n * 8 + 2 * lt;
                if (col > row0)         c[n][0] = -1e30f;
                if (col + 1 > row0)     c[n][1] = -1e30f;
                if (col > row0 + 8)     c[n][2] = -1e30f;
                if (col + 1 > row0 + 8) c[n][3] = -1e30f;
            }
        }
        float mx0 = -1e30f, mx1 = -1e30f;
#pragma unroll
        for (int n = 0; n < 8; n++) {
            mx0 = fmaxf(mx0, fmaxf(c[n][0], c[n][1]));
            mx1 = fmaxf(mx1, fmaxf(c[n][2], c[n][3]));
        }
        mx0 = fmaxf(mx0, __shfl_xor_sync(0xffffffffu, mx0, 1));
        mx0 = fmaxf(mx0, __shfl_xor_sync(0xffffffffu, mx0, 2));
        mx1 = fmaxf(mx1, __shfl_xor_sync(0xffffffffu, mx1, 1));
        mx1 = fmaxf(mx1, __shfl_xor_sync(0xffffffffu, mx1, 2));

        float mn0 = fmaxf(m0r, mx0);
        float mn1 = fmaxf(m1r, mx1);
        float corr0 = exp2f(m0r - mn0);
        float corr1 = exp2f(m1r - mn1);

        float sum0 = 0.f, sum1 = 0.f;
        {
            const int r0 = w * 16 + lg;
            uint32_t p0base = psb + (uint32_t)(r0 * PH + lt * 4);
            uint32_t p1base = psb + (uint32_t)((r0 + 8) * PH + lt * 4);
#pragma unroll
            for (int n = 0; n < 8; n++) {
                float p00 = exp2f(c[n][0] - mn0);
                float p01 = exp2f(c[n][1] - mn0);
                float p10 = exp2f(c[n][2] - mn1);
                float p11 = exp2f(c[n][3] - mn1);
                sum0 += p00 + p01;
                sum1 += p10 + p11;
                uint32_t w0 = pack_h2(p00, p01);
                uint32_t w1 = pack_h2(p10, p11);
                asm volatile("st.shared.b32 [%0], %1;" :: "r"(p0base + n * 16), "r"(w0));
                asm volatile("st.shared.b32 [%0], %1;" :: "r"(p1base + n * 16), "r"(w1));
            }
        }
        // lane-partial l (corr uniform across lt-quad; reduce deferred to epilogue)
        l0r = l0r * corr0 + sum0;
        l1r = l1r * corr1 + sum1;
        m0r = mn0;
        m1r = mn1;
#pragma unroll
        for (int n = 0; n < 8; n++) {
            o[n][0] *= corr0;
            o[n][1] *= corr0;
            o[n][2] *= corr1;
            o[n][3] *= corr1;
        }
        __syncwarp();
    };

    auto pv = [&](uint32_t psb, float (&o)[8][4], int buf) {
        uint32_t vb = vbase(buf);
#pragma unroll
        for (int ks = 0; ks < 4; ks++) {
            uint32_t pa[4];
            uint32_t paddr = psb + (uint32_t)(p_row * PH + ks * 32 + p_colb);
            LDSM_X4(pa[0], pa[1], pa[2], pa[3], paddr);
#pragma unroll
            for (int jp = 0; jp < 4; jp++) {
                uint32_t v0, v1, v2, v3;
                uint32_t addr = vb + (uint32_t)((jp * 16 + k_row) * PH + ks * 32 + k_colb);
                LDSM_X4(v0, v1, v2, v3, addr);
                mma_f16(o[2 * jp], pa, v0, v1);
                mma_f16(o[2 * jp + 1], pa, v2, v3);
            }
        }
    };

    // prologue
    stage(0, 0);
    CP_COMMIT();

    // joint loop: both tiles active for kt in [0, qtA]; stage always valid (kt+1 <= qtB)
    for (int kt = 0; kt <= qtA; kt++) {
        const int cur = kt & 1;
        stage(kt + 1, cur ^ 1);
        CP_COMMIT();
        CP_WAIT(1);
        __syncthreads();

        qk(aqA, cur);
        softmax_t(psA, mA0, mA1, lA0, lA1, oA, kt == qtA);
        qk(aqB, cur);                 // c reused; independent of softmax_A tail
        pv(psA, oA, cur);             // covers softmax_B's dependency window
        softmax_t(psB, mB0, mB1, lB0, lB1, oB, false);
        pv(psB, oB, cur);

        __syncthreads();
    }

    // solo iteration for tile B: kt = qtB (diagonal)
    {
        const int cur = qtB & 1;
        CP_WAIT(0);
        __syncthreads();
        qk(aqB, cur);
        softmax_t(psB, mB0, mB1, lB0, lB1, oB, true);
        pv(psB, oB, cur);
    }

    // final cross-lane l reduction
    lA0 += __shfl_xor_sync(0xffffffffu, lA0, 1);
    lA0 += __shfl_xor_sync(0xffffffffu, lA0, 2);
    lA1 += __shfl_xor_sync(0xffffffffu, lA1, 1);
    lA1 += __shfl_xor_sync(0xffffffffu, lA1, 2);
    lB0 += __shfl_xor_sync(0xffffffffu, lB0, 1);
    lB0 += __shfl_xor_sync(0xffffffffu, lB0, 2);
    lB1 += __shfl_xor_sync(0xffffffffu, lB1, 1);
    lB1 += __shfl_xor_sync(0xffffffffu, lB1, 2);

    // ---- write normalized outputs as fp16 hi/lo ----
    auto write_out = [&](float (&o)[8][4], float l0, float l1, int qt) {
        float inv0 = 1.f / l0;
        float inv1 = 1.f / l1;
        const int r0 = qt * 64 + w * 16 + lg;
        size_t base0 = ((size_t)b * S + r0) * HIDDEN + h * HD + 2 * lt;
        size_t base1 = ((size_t)b * S + r0 + 8) * HIDDEN + h * HD + 2 * lt;
#pragma unroll
        for (int n = 0; n < 8; n++) {
            uint32_t hi, lo;
            split2h(o[n][0] * inv0, o[n][1] * inv0, hi, lo);
            Ohi[(base0 + n * 8) >> 1] = hi;
            Olo[(base0 + n * 8) >> 1] = lo;
            split2h(o[n][2] * inv1, o[n][3] * inv1, hi, lo);
            Ohi[(base1 + n * 8) >> 1] = hi;
            Olo[(base1 + n * 8) >> 1] = lo;
        }
    };
    write_out(oA, lA0, lA1, qtA);
    write_out(oB, lB0, lB1, qtB);
}

// ---------------- launch ----------------
extern "C" void kernel_launch(void* const* d_in, const int* in_sizes, int n_in,
                              void* d_out, int out_size) {
    const float* hs = (const float*)d_in[0];
    const float* Wq = (const float*)d_in[2];
    const float* bq = (const float*)d_in[3];
    const float* Wk = (const float*)d_in[4];
    const float* bk = (const float*)d_in[5];
    const float* Wv = (const float*)d_in[6];
    const float* bv = (const float*)d_in[7];
    const float* Wo = (const float*)d_in[8];
    float* out = (float*)d_out;

    __half *qh, *kh, *vth;
    float2* rope;
    uint2 *ah, *al;
    cudaGetSymbolAddress((void**)&qh, g_qh);
    cudaGetSymbolAddress((void**)&kh, g_kh);
    cudaGetSymbolAddress((void**)&vth, g_vth);
    cudaGetSymbolAddress((void**)&rope, g_rope);
    cudaGetSymbolAddress((void**)&ah, g_ah);
    cudaGetSymbolAddress((void**)&al, g_al);

    static bool attr_set = false;
    if (!attr_set) {
        cudaFuncSetAttribute(attn_kernel, cudaFuncAttributeMaxDynamicSharedMemorySize, ATTN_SMEM);
        cudaFuncSetAttribute(gemm_qkv, cudaFuncAttributeMaxDynamicSharedMemorySize, G1_SMEM);
        cudaFuncSetAttribute(gemm_out, cudaFuncAttributeMaxDynamicSharedMemorySize, G2_SMEM);
        attr_set = true;
    }

    build_rope<<<(S * 32) / 256, 256>>>(rope);
    conv_h<<<(TOT4 + 255) / 256, 256>>>((const float4*)hs, (const float4*)Wq,
                                        (const float4*)Wk, (const float4*)Wv,
                                        (const float4*)Wo);

    gemm_qkv<<<dim3(18, MTOK / 128), 128, G1_SMEM>>>(bq, bk, bv, rope, qh, kh, vth);

    // paired q-tiles: grid.x = S/128 pairs
    attn_kernel<<<dim3(S / 128, NH, B), 128, ATTN_SMEM>>>(qh, kh, vth,
                                                          (uint32_t*)ah, (uint32_t*)al);

    gemm_out<<<dim3(HIDDEN / 64, MTOK / 128), 128, G2_SMEM>>>(out);
}